// round 1
// baseline (speedup 1.0000x reference)
#include <cuda_runtime.h>
#include <math.h>

// Problem constants
#define BB 2
#define TT 2048
#define CC 1024
#define HH 16
#define HD 64
#define M_ROWS (BB*TT)        // 4096
#define QKV_N  (3*CC)         // 3072

// Scratch (no cudaMalloc allowed)
__device__ float g_qkv[(size_t)M_ROWS * QKV_N];  // [4096, 3072]
__device__ float g_y  [(size_t)M_ROWS * CC];     // [4096, 1024]

// ---------------------------------------------------------------------------
// SGEMM: C[M,N] = A[M,K] @ B[K,N] + bias[N]
// BM=128, BN=128, BK=8, TM=8, TN=8, 256 threads
// M % 128 == 0, N % 128 == 0, K % 8 == 0 (true for all our shapes)
// ---------------------------------------------------------------------------
#define GBM 128
#define GBN 128
#define GBK 8
#define GTM 8
#define GTN 8

__global__ __launch_bounds__(256) void sgemm_bias(
    int M, int N, int K,
    const float* __restrict__ A,
    const float* __restrict__ B,
    const float* __restrict__ bias,
    float* __restrict__ C)
{
    __shared__ float As[GBK][GBM];   // transposed A tile
    __shared__ float Bs[GBK][GBN];

    const int tid  = threadIdx.x;
    const int brow = blockIdx.y;
    const int bcol = blockIdx.x;

    const float* Ap = A + (size_t)brow * GBM * K;
    const float* Bp = B + (size_t)bcol * GBN;
    float*       Cp = C + (size_t)brow * GBM * N + (size_t)bcol * GBN;

    // A tile: 128x8 -> 256 float4 loads, one per thread
    const int aRow = tid >> 1;          // 0..127
    const int aCol = (tid & 1) * 4;     // 0 or 4
    // B tile: 8x128 -> 256 float4 loads
    const int bRow = tid >> 5;          // 0..7
    const int bCol = (tid & 31) * 4;    // 0..124

    const int tRow = (tid >> 4) * GTM;  // 0..120
    const int tCol = (tid & 15) * GTN;  // 0..120

    float acc[GTM][GTN];
#pragma unroll
    for (int i = 0; i < GTM; i++)
#pragma unroll
        for (int j = 0; j < GTN; j++) acc[i][j] = 0.0f;

    float ra[GTM], rb[GTN];

    for (int k0 = 0; k0 < K; k0 += GBK) {
        float4 a4 = *reinterpret_cast<const float4*>(Ap + (size_t)aRow * K + aCol);
        As[aCol + 0][aRow] = a4.x;
        As[aCol + 1][aRow] = a4.y;
        As[aCol + 2][aRow] = a4.z;
        As[aCol + 3][aRow] = a4.w;
        *reinterpret_cast<float4*>(&Bs[bRow][bCol]) =
            *reinterpret_cast<const float4*>(Bp + (size_t)bRow * N + bCol);
        __syncthreads();

#pragma unroll
        for (int k = 0; k < GBK; k++) {
#pragma unroll
            for (int i = 0; i < GTM; i++) ra[i] = As[k][tRow + i];
#pragma unroll
            for (int j = 0; j < GTN; j++) rb[j] = Bs[k][tCol + j];
#pragma unroll
            for (int i = 0; i < GTM; i++)
#pragma unroll
                for (int j = 0; j < GTN; j++)
                    acc[i][j] = fmaf(ra[i], rb[j], acc[i][j]);
        }
        __syncthreads();

        Ap += GBK;
        Bp += (size_t)GBK * N;
    }

    const float* biasp = bias + (size_t)bcol * GBN;
#pragma unroll
    for (int i = 0; i < GTM; i++) {
#pragma unroll
        for (int j = 0; j < GTN; j += 4) {
            float4 v;
            v.x = acc[i][j + 0] + biasp[tCol + j + 0];
            v.y = acc[i][j + 1] + biasp[tCol + j + 1];
            v.z = acc[i][j + 2] + biasp[tCol + j + 2];
            v.w = acc[i][j + 3] + biasp[tCol + j + 3];
            *reinterpret_cast<float4*>(Cp + (size_t)(tRow + i) * N + tCol + j) = v;
        }
    }
}

// ---------------------------------------------------------------------------
// Flash attention (causal), fp32.
// grid: (B*H, T/128). block: 128 threads, each thread owns one q row.
// KV tiles of 32 rows staged in smem; scores kept in registers.
// qkv layout: row (b*T+t), cols: Q at [h*64+d], K at [1024 + h*64+d],
// V at [2048 + h*64+d].
// ---------------------------------------------------------------------------
#define BQ 128
#define BKV 32

__global__ __launch_bounds__(BQ) void attn_kernel(
    const float* __restrict__ qkv, float* __restrict__ y)
{
    const int bh = blockIdx.x;
    const int b  = bh / HH;
    const int h  = bh % HH;
    const int qt = blockIdx.y;
    const int tidx = threadIdx.x;
    const int qrow = qt * BQ + tidx;

    __shared__ float4 Ks[BKV][HD / 4];   // 8 KB
    __shared__ float4 Vs[BKV][HD / 4];   // 8 KB

    const float scale = 0.125f; // 1/sqrt(64)

    // Load this thread's q row into registers (pre-scaled)
    float4 q4[HD / 4];
    {
        const float* qptr = qkv + ((size_t)(b * TT + qrow)) * QKV_N + h * HD;
#pragma unroll
        for (int i = 0; i < HD / 4; i++) {
            float4 v = *reinterpret_cast<const float4*>(qptr + 4 * i);
            v.x *= scale; v.y *= scale; v.z *= scale; v.w *= scale;
            q4[i] = v;
        }
    }

    float4 o4[HD / 4];
#pragma unroll
    for (int i = 0; i < HD / 4; i++) o4[i] = make_float4(0.f, 0.f, 0.f, 0.f);
    float m = -1e30f, l = 0.0f;

    const float* kbase = qkv + ((size_t)b * TT) * QKV_N + CC      + h * HD;
    const float* vbase = qkv + ((size_t)b * TT) * QKV_N + 2 * CC  + h * HD;

    const int ntiles = 4 * qt + 4;  // covers k in [0, qt*128+128)

    for (int kt = 0; kt < ntiles; kt++) {
        const int kb = kt * BKV;
        __syncthreads();  // protect smem reuse from previous iteration
        // cooperative load of K/V tile: 32 rows x 16 float4 = 512 float4 each
#pragma unroll
        for (int i = 0; i < 4; i++) {
            int f = tidx + BQ * i;     // 0..511
            int r = f >> 4;            // 0..31
            int c = f & 15;            // 0..15
            size_t goff = (size_t)(kb + r) * QKV_N + 4 * c;
            Ks[r][c] = *reinterpret_cast<const float4*>(kbase + goff);
            Vs[r][c] = *reinterpret_cast<const float4*>(vbase + goff);
        }
        __syncthreads();

        const bool maskTile = (kb + BKV - 1) > qrow;

        float sreg[BKV];
        float tmax = -1e30f;
#pragma unroll 4
        for (int j = 0; j < BKV; j++) {
            float s = 0.0f;
#pragma unroll
            for (int d = 0; d < HD / 4; d++) {
                float4 kv = Ks[j][d];
                s = fmaf(q4[d].x, kv.x, s);
                s = fmaf(q4[d].y, kv.y, s);
                s = fmaf(q4[d].z, kv.z, s);
                s = fmaf(q4[d].w, kv.w, s);
            }
            if (maskTile && (kb + j) > qrow) s = -1e30f;
            sreg[j] = s;
            tmax = fmaxf(tmax, s);
        }

        float mnew = fmaxf(m, tmax);
        float alpha = __expf(m - mnew);
        l *= alpha;
#pragma unroll
        for (int d = 0; d < HD / 4; d++) {
            o4[d].x *= alpha; o4[d].y *= alpha;
            o4[d].z *= alpha; o4[d].w *= alpha;
        }
        m = mnew;

#pragma unroll 4
        for (int j = 0; j < BKV; j++) {
            float p = __expf(sreg[j] - mnew);
            l += p;
#pragma unroll
            for (int d = 0; d < HD / 4; d++) {
                float4 vv = Vs[j][d];
                o4[d].x = fmaf(p, vv.x, o4[d].x);
                o4[d].y = fmaf(p, vv.y, o4[d].y);
                o4[d].z = fmaf(p, vv.z, o4[d].z);
                o4[d].w = fmaf(p, vv.w, o4[d].w);
            }
        }
    }

    const float inv = 1.0f / l;
    float* yptr = y + ((size_t)(b * TT + qrow)) * CC + h * HD;
#pragma unroll
    for (int i = 0; i < HD / 4; i++) {
        float4 v = o4[i];
        v.x *= inv; v.y *= inv; v.z *= inv; v.w *= inv;
        *reinterpret_cast<float4*>(yptr + 4 * i) = v;
    }
}

// ---------------------------------------------------------------------------
extern "C" void kernel_launch(void* const* d_in, const int* in_sizes, int n_in,
                              void* d_out, int out_size)
{
    const float* x     = (const float*)d_in[0];
    const float* w_qkv = (const float*)d_in[1];
    const float* b_qkv = (const float*)d_in[2];
    const float* w_out = (const float*)d_in[3];
    const float* b_out = (const float*)d_in[4];
    float* out = (float*)d_out;

    float* qkv_buf = nullptr;
    float* y_buf   = nullptr;
    cudaGetSymbolAddress((void**)&qkv_buf, g_qkv);
    cudaGetSymbolAddress((void**)&y_buf,   g_y);

    // 1) qkv = x @ w_qkv + b_qkv   (4096 x 3072 x 1024)
    {
        dim3 grid(QKV_N / GBN, M_ROWS / GBM);
        sgemm_bias<<<grid, 256>>>(M_ROWS, QKV_N, CC, x, w_qkv, b_qkv, qkv_buf);
    }

    // 2) flash attention -> y
    {
        dim3 grid(BB * HH, TT / BQ);
        attn_kernel<<<grid, BQ>>>(qkv_buf, y_buf);
    }

    // 3) out = y @ w_out + b_out   (4096 x 1024 x 1024)
    {
        dim3 grid(CC / GBN, M_ROWS / GBM);
        sgemm_bias<<<grid, 256>>>(M_ROWS, CC, CC, y_buf, w_out, b_out, out);
    }
}